// round 1
// baseline (speedup 1.0000x reference)
#include <cuda_runtime.h>
#include <cstdint>

// Problem constants
#define BATCH      16384
#define SEQ        15
#define DIM        512
#define UNITS      32
#define NQK        64      // q|k concatenated output width
#define CTA_BATCH  8
#define ROWS       120     // CTA_BATCH * SEQ
#define THREADS    256
#define KCHUNK     32

// smem layout (floats)
#define XS_STRIDE  36
#define WS_STRIDE  36
#define QK_STRIDE  65
#define EA_STRIDE  16
#define XS_OFF     0                       // [128][36]  = 4608
#define WS_OFF     4608                    // [64][36]   = 2304
#define QK_OFF     6912                    // [120][65]  = 7800
#define EA_OFF     14712                   // [8][15][16]= 1920
#define WA_OFF     16632                   // 32
#define BH_OFF     16664                   // 32
#define SMEM_FLOATS 16696
#define SMEM_BYTES (SMEM_FLOATS * 4)

__device__ __forceinline__ uint32_t tf32_bits(float f) {
    uint32_t u;
    asm("cvt.rna.tf32.f32 %0, %1;" : "=r"(u) : "f"(f));
    return u;
}

__device__ __forceinline__ void mma_tf32(float* c,
                                         uint32_t a0, uint32_t a1, uint32_t a2, uint32_t a3,
                                         uint32_t b0, uint32_t b1) {
    asm volatile(
        "mma.sync.aligned.m16n8k8.row.col.f32.tf32.tf32.f32 "
        "{%0,%1,%2,%3}, {%4,%5,%6,%7}, {%8,%9}, {%0,%1,%2,%3};"
        : "+f"(c[0]), "+f"(c[1]), "+f"(c[2]), "+f"(c[3])
        : "r"(a0), "r"(a1), "r"(a2), "r"(a3), "r"(b0), "r"(b1));
}

__global__ __launch_bounds__(THREADS, 2)
void sda_fused_kernel(const float* __restrict__ x,
                      const float* __restrict__ Wt,
                      const float* __restrict__ Wx,
                      const float* __restrict__ bh,
                      const float* __restrict__ Wa,
                      const float* __restrict__ ba,
                      float* __restrict__ out)
{
    extern __shared__ float sm[];
    float* xs  = sm + XS_OFF;
    float* ws  = sm + WS_OFF;
    float* qs  = sm + QK_OFF;
    float* ea  = sm + EA_OFF;
    float* was = sm + WA_OFF;
    float* bhs = sm + BH_OFF;

    const int tid  = threadIdx.x;
    const int lane = tid & 31;
    const int w    = tid >> 5;          // warp id 0..7
    const int cta  = blockIdx.x;
    const long long rowbase = (long long)cta * ROWS;

    if (tid < UNITS) { was[tid] = Wa[tid]; bhs[tid] = bh[tid]; }
    const float bav = ba[0];

    // ---------------- Phase 1: qk = x @ [Wt|Wx] (tf32 mma.sync) -------------
    float acc[8][4];
    #pragma unroll
    for (int n = 0; n < 8; n++)
        #pragma unroll
        for (int q = 0; q < 4; q++) acc[n][q] = 0.f;

    const int g  = lane >> 2;   // 0..7
    const int tg = lane & 3;    // 0..3

    for (int kc = 0; kc < DIM; kc += KCHUNK) {
        __syncthreads();  // previous chunk's mma done (and covers was/bhs init)

        // stage W^T chunk: ws[n][k] (tf32-rounded)
        #pragma unroll
        for (int r = 0; r < 8; r++) {
            int e = tid + THREADS * r;          // 0..2047
            int k = e >> 6;                     // 0..31
            int n = e & 63;                     // 0..63
            float v = (n < UNITS) ? Wt[(kc + k) * UNITS + n]
                                  : Wx[(kc + k) * UNITS + (n - UNITS)];
            ws[n * WS_STRIDE + k] = __uint_as_float(tf32_bits(v));
        }
        // stage x chunk: xs[row][k] (tf32-rounded), rows >= ROWS zero-padded
        #pragma unroll
        for (int r4 = 0; r4 < 4; r4++) {
            int f   = tid + THREADS * r4;       // 0..1023 float4 slots
            int row = f >> 3;                   // 0..127
            int c4  = f & 7;                    // 0..7
            float4 v = make_float4(0.f, 0.f, 0.f, 0.f);
            if (row < ROWS)
                v = *(const float4*)(x + (rowbase + row) * DIM + kc + c4 * 4);
            v.x = __uint_as_float(tf32_bits(v.x));
            v.y = __uint_as_float(tf32_bits(v.y));
            v.z = __uint_as_float(tf32_bits(v.z));
            v.w = __uint_as_float(tf32_bits(v.w));
            *(float4*)(xs + row * XS_STRIDE + c4 * 4) = v;
        }
        __syncthreads();

        #pragma unroll
        for (int k8 = 0; k8 < 4; k8++) {
            const int kb = k8 * 8;
            const float* ar = xs + (w * 16 + g) * XS_STRIDE + kb + tg;
            uint32_t a0 = __float_as_uint(ar[0]);
            uint32_t a1 = __float_as_uint(ar[8 * XS_STRIDE]);
            uint32_t a2 = __float_as_uint(ar[4]);
            uint32_t a3 = __float_as_uint(ar[8 * XS_STRIDE + 4]);
            #pragma unroll
            for (int nt = 0; nt < 8; nt++) {
                const float* br = ws + (nt * 8 + g) * WS_STRIDE + kb + tg;
                uint32_t b0 = __float_as_uint(br[0]);
                uint32_t b1 = __float_as_uint(br[4]);
                mma_tf32(acc[nt], a0, a1, a2, a3, b0, b1);
            }
        }
    }

    // epilogue: write qk to smem, folding bh into the q columns (cols < 32)
    {
        const int r0 = w * 16 + g;
        const int r1 = r0 + 8;
        #pragma unroll
        for (int nt = 0; nt < 8; nt++) {
            int c = nt * 8 + tg * 2;
            float b0 = (c     < UNITS) ? bhs[c]     : 0.f;
            float b1 = (c + 1 < UNITS) ? bhs[c + 1] : 0.f;
            if (r0 < ROWS) {
                qs[r0 * QK_STRIDE + c]     = acc[nt][0] + b0;
                qs[r0 * QK_STRIDE + c + 1] = acc[nt][1] + b1;
            }
            if (r1 < ROWS) {
                qs[r1 * QK_STRIDE + c]     = acc[nt][2] + b0;
                qs[r1 * QK_STRIDE + c + 1] = acc[nt][3] + b1;
            }
        }
    }
    __syncthreads();

    // ------------- Phase 2: e = Wa . tanh(q_i + k_j) + ba + mask; softmax ---
    // warp w handles local batch w (rows w*SEQ .. w*SEQ+14)
    float* eaw = ea + w * SEQ * EA_STRIDE;

    for (int p = lane; p < SEQ * SEQ; p += 32) {
        int i = p / SEQ;
        int j = p - i * SEQ;
        const float* qi = qs + (w * SEQ + i) * QK_STRIDE;
        const float* kj = qs + (w * SEQ + j) * QK_STRIDE + UNITS;
        float s = 0.f;
        #pragma unroll
        for (int u = 0; u < UNITS; u++)
            s += was[u] * tanhf(qi[u] + kj[u]);
        float mask = (i == j) ? -10000.f : -fabsf((float)(i - j));
        eaw[i * EA_STRIDE + j] = s + bav + mask;
    }
    __syncwarp();

    if (lane < SEQ) {
        const int i = lane;
        float m = -1e30f;
        #pragma unroll
        for (int j = 0; j < SEQ; j++) m = fmaxf(m, eaw[i * EA_STRIDE + j]);
        float ex[SEQ];
        float sum = 0.f;
        #pragma unroll
        for (int j = 0; j < SEQ; j++) {
            ex[j] = __expf(eaw[i * EA_STRIDE + j] - m);
            sum += ex[j];
        }
        float inv = 1.f / sum;
        #pragma unroll
        for (int j = 0; j < SEQ; j++) eaw[i * EA_STRIDE + j] = ex[j] * inv;
    }
    __syncwarp();

    // ---------------- Phase 3: v = a @ x (per-warp, float4) -----------------
    const long long bb = (rowbase + (long long)w * SEQ) * DIM;
    const float* xb = x + bb;
    float* ob = out + bb;

    #pragma unroll 1
    for (int dc = 0; dc < DIM; dc += 128) {
        float4 xj[SEQ];
        #pragma unroll
        for (int j = 0; j < SEQ; j++)
            xj[j] = *(const float4*)(xb + j * DIM + dc + lane * 4);

        // i = 0..7
        {
            float4 av[8];
            #pragma unroll
            for (int i = 0; i < 8; i++) av[i] = make_float4(0.f, 0.f, 0.f, 0.f);
            #pragma unroll
            for (int j = 0; j < SEQ; j++) {
                #pragma unroll
                for (int i = 0; i < 8; i++) {
                    float a = eaw[i * EA_STRIDE + j];
                    av[i].x += a * xj[j].x;
                    av[i].y += a * xj[j].y;
                    av[i].z += a * xj[j].z;
                    av[i].w += a * xj[j].w;
                }
            }
            #pragma unroll
            for (int i = 0; i < 8; i++)
                *(float4*)(ob + i * DIM + dc + lane * 4) = av[i];
        }
        // i = 8..14
        {
            float4 av[7];
            #pragma unroll
            for (int i = 0; i < 7; i++) av[i] = make_float4(0.f, 0.f, 0.f, 0.f);
            #pragma unroll
            for (int j = 0; j < SEQ; j++) {
                #pragma unroll
                for (int i = 0; i < 7; i++) {
                    float a = eaw[(i + 8) * EA_STRIDE + j];
                    av[i].x += a * xj[j].x;
                    av[i].y += a * xj[j].y;
                    av[i].z += a * xj[j].z;
                    av[i].w += a * xj[j].w;
                }
            }
            #pragma unroll
            for (int i = 0; i < 7; i++)
                *(float4*)(ob + (i + 8) * DIM + dc + lane * 4) = av[i];
        }
    }
}

extern "C" void kernel_launch(void* const* d_in, const int* in_sizes, int n_in,
                              void* d_out, int out_size) {
    const float* x  = (const float*)d_in[0];
    const float* Wt = (const float*)d_in[1];
    const float* Wx = (const float*)d_in[2];
    const float* bh = (const float*)d_in[3];
    const float* Wa = (const float*)d_in[4];
    const float* ba = (const float*)d_in[5];
    float* out = (float*)d_out;

    cudaFuncSetAttribute(sda_fused_kernel,
                         cudaFuncAttributeMaxDynamicSharedMemorySize, SMEM_BYTES);

    sda_fused_kernel<<<BATCH / CTA_BATCH, THREADS, SMEM_BYTES>>>(
        x, Wt, Wx, bh, Wa, ba, out);
}